// round 4
// baseline (speedup 1.0000x reference)
#include <cuda_runtime.h>
#include <cuda_bf16.h>
#include <cstdint>
#include <cmath>

#define T_LEN 1024
#define NH    512
#define NI    128
#define BSZ   64
#define DT_C  0.1f

// Hoisted input projection scratch: tanh(x @ x2h), [B, T, H] fp32 (134 MB).
__device__ float g_tanhI[(size_t)BSZ * T_LEN * NH];

typedef unsigned long long ull;

// ---------------------------------------------------------------------------
// helpers
// ---------------------------------------------------------------------------
__device__ __forceinline__ uint32_t smem_u32(const void* p) {
    uint32_t a;
    asm("{ .reg .u64 t; cvta.to.shared.u64 t, %1; cvt.u32.u64 %0, t; }" : "=r"(a) : "l"(p));
    return a;
}
__device__ __forceinline__ uint32_t mapa_sc(uint32_t addr, uint32_t rank) {
    uint32_t r;
    asm("mapa.shared::cluster.u32 %0, %1, %2;" : "=r"(r) : "r"(addr), "r"(rank));
    return r;
}
__device__ __forceinline__ void st_dsm_v2(uint32_t addr, ull a, ull b) {
    asm volatile("st.shared::cluster.v2.b64 [%0], {%1, %2};"
                 :: "r"(addr), "l"(a), "l"(b) : "memory");
}
__device__ __forceinline__ void cluster_sync_() {
    asm volatile("barrier.cluster.arrive.aligned;" ::: "memory");
    asm volatile("barrier.cluster.wait.aligned;" ::: "memory");
}
__device__ __forceinline__ ull pack2(float w) {
    ull r;
    asm("mov.b64 %0, {%1, %1};" : "=l"(r) : "f"(w));
    return r;
}
__device__ __forceinline__ void ffma2(ull& d, ull a, ull b) {
    asm("fma.rn.f32x2 %0, %1, %2, %0;" : "+l"(d) : "l"(a), "l"(b));
}
__device__ __forceinline__ ull addf2(ull a, ull b) {
    ull d;
    asm("add.rn.f32x2 %0, %1, %2;" : "=l"(d) : "l"(a), "l"(b));
    return d;
}
__device__ __forceinline__ void bfly_red2(ull& v) {   // sum over 4-lane groups
    ull o = __shfl_xor_sync(0xffffffffu, v, 1);
    v = addf2(v, o);
    o = __shfl_xor_sync(0xffffffffu, v, 2);
    v = addf2(v, o);
}

// ---------------------------------------------------------------------------
// Phase 1: g_tanhI[bt, h] = tanh( x[bt, :] @ x2h[:, h] )
// ---------------------------------------------------------------------------
__global__ void __launch_bounds__(256) phase1_kernel(const float* __restrict__ x,
                                                     const float* __restrict__ x2h) {
    __shared__ float  x_s[16 * 132];
    __shared__ float4 w4_s[128 * 16];
    const int tid = threadIdx.x;
    const int bt0 = blockIdx.x * 16;

    for (int i = tid; i < 512; i += 256) {
        int r = i >> 5, c = i & 31;
        float4 v = *reinterpret_cast<const float4*>(x + (size_t)(bt0 + r) * NI + c * 4);
        *reinterpret_cast<float4*>(x_s + r * 132 + c * 4) = v;
    }

    const int tt = tid & 15;
    const int jc = tid >> 4;
    for (int chunk = 0; chunk < 8; ++chunk) {
        __syncthreads();
        const int jbase = chunk * 64;
        for (int i = tid; i < 2048; i += 256) {
            int k = i >> 4, jq = i & 15;
            w4_s[k * 16 + jq] =
                *reinterpret_cast<const float4*>(x2h + (size_t)k * NH + jbase + jq * 4);
        }
        __syncthreads();
        float a0 = 0.f, a1 = 0.f, a2 = 0.f, a3 = 0.f;
        #pragma unroll 8
        for (int k = 0; k < 128; ++k) {
            float  xv = x_s[tt * 132 + k];
            float4 w  = w4_s[k * 16 + jc];
            a0 = fmaf(xv, w.x, a0); a1 = fmaf(xv, w.y, a1);
            a2 = fmaf(xv, w.z, a2); a3 = fmaf(xv, w.w, a3);
        }
        float4 o = make_float4(tanhf(a0), tanhf(a1), tanhf(a2), tanhf(a3));
        *reinterpret_cast<float4*>(g_tanhI + (size_t)(bt0 + tt) * NH + jbase + jc * 4) = o;
    }
}

// ---------------------------------------------------------------------------
// Phase 2: recurrence. 16 clusters x 8 CTAs x 512 threads.
// CTA rank owns hidden cols J=[64r,64r+64); wT[j][k] resident, stride 516.
//
// SMEM float layout:
//   [0)      wT      64*516 = 33024
//   [33024)  hyP     4*520  (hy[m][k], m-major, k-packed reads)
//   [35104)  stg     2048 u64 = 4096 fl  ([ks][m][jg] f32x2 partials)
//   [39200)  pd      256 u64 = 512 fl    (pre duplicated: [j][m] = {p,p})
//   [39712)  red     8*4*64 = 2048       ([src][m][kl])
//   [41760)  hystage 4*64 = 256          ([m][kl])
//   [42016)  bias    64
//   total 42080 floats = 168320 B
// ---------------------------------------------------------------------------
#define WS        516
#define HYPS      520
#define W_OFF     0
#define HYP_OFF   33024
#define STG_OFF   35104
#define PD_OFF    39200
#define RED_OFF   39712
#define HYST_OFF  41760
#define BIAS_OFF  42016
#define SMEM_FLOATS 42080
#define SMEM_BYTES  (SMEM_FLOATS * 4)

__global__ void __launch_bounds__(512)
rnn_kernel(const float* __restrict__ h2h, const float* __restrict__ bias,
           const float* __restrict__ gamma_v, const float* __restrict__ eps_v,
           float* __restrict__ out_states, float* __restrict__ out_hy) {
    extern __shared__ float sm[];
    float* bias_s = sm + BIAS_OFF;
    ull*   stg64  = reinterpret_cast<ull*>(sm + STG_OFF);
    ull*   pd64   = reinterpret_cast<ull*>(sm + PD_OFF);

    const int tid = threadIdx.x;
    uint32_t rank;
    asm("mov.u32 %0, %%cluster_ctarank;" : "=r"(rank));
    const int m_base = (blockIdx.x >> 3) * 4;
    const int J0 = (int)rank * 64;
    const uint32_t smb = smem_u32(sm);

    // --- init: weight slice wT[j][k] = h2h[k][J0+j], bias, zero hyP ---
    for (int idx = tid; idx < 64 * 512; idx += 512) {
        int k = idx >> 6, jl = idx & 63;
        sm[W_OFF + jl * WS + k] = h2h[(size_t)k * NH + J0 + jl];
    }
    if (tid < 64) bias_s[tid] = bias[J0 + tid];
    for (int i = tid; i < 4 * HYPS; i += 512) sm[HYP_OFF + i] = 0.f;

    // --- fixed thread mappings ---
    const int ks = tid >> 6;              // GEMM1 k-split 0..7
    const int jg = tid & 63;              // GEMM1 local j
    const int kq = tid >> 2;              // GEMM2 k-quad 0..127
    const int js = tid & 3;               // GEMM2 j-split 0..3
    const int m_u  = tid >> 6;            // update mapping (tid<256)
    const int kl_u = tid & 63;
    const int k_own = J0 + kl_u;

    // hoisted DSMEM addresses
    const uint32_t red_dst =
        mapa_sc(smb + RED_OFF * 4, (uint32_t)(kq >> 4)) +
        (uint32_t)(((int)rank * 256 + js * 64 + (kq & 15) * 4) * 4);
    const int bc_r  = tid >> 6;           // broadcast target rank
    const int bc_m  = (tid & 63) >> 4;
    const int bc_kq = tid & 15;
    const uint32_t hyb_dst =
        mapa_sc(smb + HYP_OFF * 4, (uint32_t)bc_r) +
        (uint32_t)((bc_m * HYPS + J0 + bc_kq * 4) * 4);

    float hy_r = 0.f, hz_r = 0.f, g_r = 0.f, e_r = 0.f, tI = 0.f;
    size_t row_base = 0;
    if (tid < 256) {
        g_r = gamma_v[k_own];
        e_r = eps_v[k_own];
        row_base = (size_t)(m_base + m_u) * T_LEN * NH + k_own;
        tI = g_tanhI[row_base];
    }

    __syncthreads();
    cluster_sync_();

    const ulonglong2* w1p  = reinterpret_cast<const ulonglong2*>(sm + W_OFF + jg * WS + ks * 64);
    const ulonglong2* hyp2 = reinterpret_cast<const ulonglong2*>(sm + HYP_OFF);
    const ulonglong2* w2p  = reinterpret_cast<const ulonglong2*>(sm + W_OFF);
    const int hb0 = 0 * 130 + ks * 16, hb1 = 1 * 130 + ks * 16;
    const int hb2 = 2 * 130 + ks * 16, hb3 = 3 * 130 + ks * 16;

    for (int t = 0; t < T_LEN; ++t) {
        // ---- GEMM1: partial pre over k-range [ks*64, ks*64+64), col J0+jg ----
        {
            ull a0 = 0, a1 = 0, a2 = 0, a3 = 0;
            #pragma unroll
            for (int i = 0; i < 16; ++i) {
                ulonglong2 w  = w1p[i];
                ulonglong2 h0 = hyp2[hb0 + i];
                ulonglong2 h1 = hyp2[hb1 + i];
                ulonglong2 h2 = hyp2[hb2 + i];
                ulonglong2 h3 = hyp2[hb3 + i];
                ffma2(a0, w.x, h0.x); ffma2(a0, w.y, h0.y);
                ffma2(a1, w.x, h1.x); ffma2(a1, w.y, h1.y);
                ffma2(a2, w.x, h2.x); ffma2(a2, w.y, h2.y);
                ffma2(a3, w.x, h3.x); ffma2(a3, w.y, h3.y);
            }
            stg64[ks * 256 +   0 + jg] = a0;
            stg64[ks * 256 +  64 + jg] = a1;
            stg64[ks * 256 + 128 + jg] = a2;
            stg64[ks * 256 + 192 + jg] = a3;
        }
        __syncthreads();
        if (tid < 256) {                     // reduce 8 ks + horizontal + tanh
            const int m = tid >> 6, j = tid & 63;
            const float2* s2 = reinterpret_cast<const float2*>(stg64) + m * 64 + j;
            float sx = 0.f, sy = 0.f;
            #pragma unroll
            for (int q = 0; q < 8; ++q) { float2 v = s2[q * 256]; sx += v.x; sy += v.y; }
            float pre = tanhf(sx + sy + bias_s[j]);
            pd64[j * 4 + m] = pack2(pre);
        }
        __syncthreads();

        // ---- GEMM2: part[m, kq*4..+3] partial over 16 j (split by js) ----
        ull b00 = 0, b01 = 0, b10 = 0, b11 = 0, b20 = 0, b21 = 0, b30 = 0, b31 = 0;
        #pragma unroll
        for (int jj = 0; jj < 16; ++jj) {
            const int j = jj * 4 + js;
            ulonglong2 w = w2p[j * 129 + kq];
            ull p0 = pd64[j * 4 + 0], p1 = pd64[j * 4 + 1];
            ull p2 = pd64[j * 4 + 2], p3 = pd64[j * 4 + 3];
            ffma2(b00, w.x, p0); ffma2(b01, w.y, p0);
            ffma2(b10, w.x, p1); ffma2(b11, w.y, p1);
            ffma2(b20, w.x, p2); ffma2(b21, w.y, p2);
            ffma2(b30, w.x, p3); ffma2(b31, w.y, p3);
        }
        // butterfly-sum over js (4-lane groups)
        bfly_red2(b00); bfly_red2(b01); bfly_red2(b10); bfly_red2(b11);
        bfly_red2(b20); bfly_red2(b21); bfly_red2(b30); bfly_red2(b31);
        // lane js scatters batch row m = js (one 16B DSMEM store per thread)
        {
            ull s0 = b00, s1 = b01;
            if (js == 1) { s0 = b10; s1 = b11; }
            else if (js == 2) { s0 = b20; s1 = b21; }
            else if (js == 3) { s0 = b30; s1 = b31; }
            st_dsm_v2(red_dst, s0, s1);
        }
        cluster_sync_();                     // partials visible

        // ---- owner reduce + state update (tid < 256) ----
        if (tid < 256) {
            int tn = (t + 1 < T_LEN) ? (t + 1) : (T_LEN - 1);
            float tI_next = g_tanhI[row_base + (size_t)tn * NH];

            float s = 0.f;
            #pragma unroll
            for (int src = 0; src < 8; ++src)
                s += sm[RED_OFF + src * 256 + m_u * 64 + kl_u];

            hz_r = hz_r + DT_C * (tI - s - g_r * hy_r - e_r * hz_r);
            hy_r = hy_r + DT_C * hz_r;
            tI = tI_next;

            out_states[(size_t)(m_base + m_u) * T_LEN * NH + (size_t)t * NH + k_own] = hy_r;
            sm[HYST_OFF + m_u * 64 + kl_u] = hy_r;
        }
        __syncthreads();

        // ---- broadcast new hy slice into every rank's hyP (16B per thread) ----
        {
            ulonglong2 hv = *reinterpret_cast<const ulonglong2*>(
                sm + HYST_OFF + bc_m * 64 + bc_kq * 4);
            st_dsm_v2(hyb_dst, hv.x, hv.y);
        }
        cluster_sync_();                     // hy visible for next GEMM1
    }

    if (tid < 256 && out_hy)
        out_hy[(size_t)(m_base + m_u) * NH + k_own] = hy_r;
}

// ---------------------------------------------------------------------------
extern "C" void kernel_launch(void* const* d_in, const int* in_sizes, int n_in,
                              void* d_out, int out_size) {
    const float* x    = (const float*)d_in[0];
    const float* x2h  = (const float*)d_in[1];
    const float* h2h  = (const float*)d_in[2];
    const float* bias = (const float*)d_in[3];
    const float* gam  = (const float*)d_in[4];
    const float* eps  = (const float*)d_in[5];
    float* out = (float*)d_out;

    const long long BTH = (long long)BSZ * T_LEN * NH;
    float* states = nullptr;
    float* hyout  = nullptr;
    if ((long long)out_size >= BTH) {
        states = out;
        if ((long long)out_size >= BTH + (long long)BSZ * NH) hyout = out + BTH;
    } else {
        hyout = out;
    }

    phase1_kernel<<<(BSZ * T_LEN) / 16, 256>>>(x, x2h);

    cudaFuncSetAttribute(rnn_kernel, cudaFuncAttributeMaxDynamicSharedMemorySize,
                         SMEM_BYTES);

    cudaLaunchConfig_t cfg = {};
    cfg.gridDim = dim3(128, 1, 1);
    cfg.blockDim = dim3(512, 1, 1);
    cfg.dynamicSmemBytes = SMEM_BYTES;
    cfg.stream = 0;
    cudaLaunchAttribute attrs[1];
    attrs[0].id = cudaLaunchAttributeClusterDimension;
    attrs[0].val.clusterDim.x = 8;
    attrs[0].val.clusterDim.y = 1;
    attrs[0].val.clusterDim.z = 1;
    cfg.attrs = attrs;
    cfg.numAttrs = 1;
    cudaLaunchKernelEx(&cfg, rnn_kernel, h2h, bias, gam, eps, states, hyout);
}